// round 10
// baseline (speedup 1.0000x reference)
#include <cuda_runtime.h>
#include <cstdint>

// Problem constants
#define NN    8192
#define NP1   8193
#define AB    16384ULL                    // A_low base (floats)
#define MM    67125249ULL                 // NP1*NP1
#define AUB   67141633ULL                 // A_up base = AB + MM
#define LR0   134258689ULL                // A_up last-row start (floats); LR0 % 4 == 1

// Flat work decomposition (one store per thread, 512-thread blocks, one wave):
//   [0, 4096)        : head float4          (conc_low|conc_up, 16384 floats)
//   [4096, 6143)     : last-row float4      (cols 3..8190, 2047 vectors)
//   [6143, 6148)     : last-row scalars     (cols 0,1,2,8191,8192)
//   [6148, 14341)    : A_low diagonal       (k = 0..8192; k=8192 -> 1.0)
//   [14341, 22533)   : A_up diagonal        (k = 0..8191)
#define W_H4   4096
#define W_LV   (W_H4 + 2047)              // 6143
#define W_LS   (W_LV + 5)                 // 6148
#define W_DL   (W_LS + NP1)               // 14341
#define W_TOT  (W_DL + NN)                // 22533

#define THREADS 512

__global__ void __launch_bounds__(THREADS) relu_relax_patch(
        const float* __restrict__ lower,
        const float* __restrict__ upper,
        const float* __restrict__ alphas,
        float* __restrict__ out) {
    const int w = blockIdx.x * THREADS + threadIdx.x;
    if (w >= W_TOT) return;

    if (w < W_H4) {
        // conc_low / conc_up, float4 per thread (16B-aligned).
        const int i0 = (w << 2) & (NN - 1);
        const float4 l4 = *reinterpret_cast<const float4*>(lower + i0);
        const float4 u4 = *reinterpret_cast<const float4*>(upper + i0);
        float4 v;
        if (w < W_H4 / 2) {
            const float4 a4 = *reinterpret_cast<const float4*>(alphas + i0);
            #define CL(lx, ux, ax) \
                (((ux) > 0.f && (lx) >= 0.f) ? (lx) : \
                 (((ux) > 0.f && (lx) < 0.f) ? fminf(fmaxf((ax),0.f),1.f)*(lx) : 0.f))
            v.x = CL(l4.x, u4.x, a4.x);
            v.y = CL(l4.y, u4.y, a4.y);
            v.z = CL(l4.z, u4.z, a4.z);
            v.w = CL(l4.w, u4.w, a4.w);
            #undef CL
        } else {
            v.x = (u4.x > 0.f) ? u4.x : 0.f;
            v.y = (u4.y > 0.f) ? u4.y : 0.f;
            v.z = (u4.z > 0.f) ? u4.z : 0.f;
            v.w = (u4.w > 0.f) ? u4.w : 0.f;
        }
        reinterpret_cast<float4*>(out)[w] = v;
        return;
    }

    if (w < W_LV) {
        // A_up last row, vectorized interior: cols c0..c0+3, c0 = 4*(w-W_H4)+3.
        const int c0 = ((w - W_H4) << 2) + 3;
        const float4 l4 = *reinterpret_cast<const float4*>(lower + c0);  // c0%4==3: unaligned OK? NO ->
        // lower+c0 is only 4B-aligned; do scalar loads to stay safe.
        float lv[4] = { lower[c0], lower[c0+1], lower[c0+2], lower[c0+3] };
        float uv[4] = { upper[c0], upper[c0+1], upper[c0+2], upper[c0+3] };
        (void)l4;
        float4 v;
        float* o = reinterpret_cast<float*>(&v);
        #pragma unroll
        for (int j = 0; j < 4; j++) {
            const float l = lv[j], u = uv[j];
            const bool unstable = (u > 0.f) && (l < 0.f);
            const float d = u - l;
            const float lam = u / ((d == 0.f) ? 1.f : d);
            o[j] = unstable ? (-lam * l) : 0.f;
        }
        // out + LR0 + c0 is 16B-aligned (LR0 % 4 == 1, c0 % 4 == 3).
        *reinterpret_cast<float4*>(out + LR0 + (size_t)c0) = v;
        return;
    }

    if (w < W_LS) {
        // Last-row scalar stragglers: cols {0,1,2,8191,8192}.
        const int t = w - W_LV;
        const int col = (t < 3) ? t : (8191 + (t - 3));
        float val;
        if (col == NN) {
            val = 1.f;
        } else {
            const float l = lower[col];
            const float u = upper[col];
            const bool unstable = (u > 0.f) && (l < 0.f);
            const float d = u - l;
            const float lam = u / ((d == 0.f) ? 1.f : d);
            val = unstable ? (-lam * l) : 0.f;
        }
        out[LR0 + (size_t)col] = val;
        return;
    }

    size_t pos;
    float  val;
    if (w < W_DL) {
        // A_low diagonal (scattered, stride 8194 floats), k = 0..8192.
        const int k = w - W_LS;
        if (k == NN) {
            val = 1.f;
        } else {
            const float l = lower[k];
            const float u = upper[k];
            const bool active   = (u > 0.f) && (l >= 0.f);
            const bool unstable = (u > 0.f) && (l < 0.f);
            const float a = fminf(fmaxf(alphas[k], 0.f), 1.f);
            val = active ? 1.f : (unstable ? a : 0.f);
        }
        pos = AB + (size_t)k * (size_t)(NP1 + 1);
    } else {
        // A_up diagonal, k = 0..8191 (k = NN is in the last-row segment).
        const int k = w - W_DL;
        const float l = lower[k];
        const float u = upper[k];
        const bool active   = (u > 0.f) && (l >= 0.f);
        const bool unstable = (u > 0.f) && (l < 0.f);
        const float d = u - l;
        const float lam = u / ((d == 0.f) ? 1.f : d);
        val = active ? 1.f : (unstable ? lam : 0.f);
        pos = AUB + (size_t)k * (size_t)(NP1 + 1);
    }
    // Scattered diagonal store: streaming (evict-first) — best measured config.
    __stcs(out + pos, val);
}

extern "C" void kernel_launch(void* const* d_in, const int* in_sizes, int n_in,
                              void* d_out, int out_size) {
    const float* lower  = (const float*)d_in[0];
    const float* upper  = (const float*)d_in[1];
    const float* alphas = (const float*)d_in[2];
    float* out = (float*)d_out;

    // Full-buffer, base-address memset: the only configuration measured at
    // the ~7.4 TB/s fast path (R1/R5). Never offset, shrink, split, or fork
    // around it (R4/R6 regressions; R2/R3/R9 SM-side fills cap at ~5.6 TB/s).
    cudaMemsetAsync(d_out, 0, (size_t)out_size * sizeof(float), 0);

    const int blocks = (W_TOT + THREADS - 1) / THREADS;   // 45
    relu_relax_patch<<<blocks, THREADS>>>(lower, upper, alphas, out);
}

// round 11
// speedup vs baseline: 1.4678x; 1.4678x over previous
#include <cuda_runtime.h>
#include <cstdint>

// Problem constants
#define NN    8192
#define NP1   8193
#define AB    16384ULL                    // A_low base (floats)
#define MM    67125249ULL                 // NP1*NP1 floats per matrix
#define AUB   67141633ULL                 // A_up base = AB + MM
#define LR0   134258689ULL                // A_up last-row start (floats)

// Flat patch segments (one store per thread; best-measured config: 512t, 81 blocks):
//   [0, 16384)      : conc_low | conc_up head            (coalesced)
//   [16384, 24577)  : A_up last row, col 0..8192          (coalesced; col 8192 -> 1)
//   [24577, 32770)  : A_low diagonal, k = 0..8192         (scattered; k 8192 -> 1)
//   [32770, 40962)  : A_up diagonal,  k = 0..8191         (scattered)
#define W_HEAD   16384
#define W_LROW   (W_HEAD + NP1)           // 24577
#define W_DLOW   (W_LROW + NP1)           // 32770
#define W_TOT    (W_DLOW + NN)            // 40962

#define THREADS 512

__global__ void __launch_bounds__(THREADS) relu_relax_patch(
        const float* __restrict__ lower,
        const float* __restrict__ upper,
        const float* __restrict__ alphas,
        float* __restrict__ out) {
    const int w = blockIdx.x * THREADS + threadIdx.x;
    if (w >= W_TOT) return;

    if (w < W_HEAD) {
        // conc_low / conc_up vectors (coalesced)
        const int i = w & (NN - 1);
        const float l = lower[i];
        const float u = upper[i];
        float val;
        if (w < NN) {
            const float a = fminf(fmaxf(alphas[i], 0.f), 1.f);
            const bool active   = (u > 0.f) && (l >= 0.f);
            const bool unstable = (u > 0.f) && (l < 0.f);
            val = active ? l : (unstable ? a * l : 0.f);
        } else {
            val = (u > 0.f) ? u : 0.f;
        }
        out[w] = val;
        return;
    }

    if (w < W_LROW) {
        // A_up last row (bias_up), col NN -> 1.0 (coalesced)
        const int col = w - W_HEAD;
        float val;
        if (col == NN) {
            val = 1.f;
        } else {
            const float l = lower[col];
            const float u = upper[col];
            const bool unstable = (u > 0.f) && (l < 0.f);
            const float d = u - l;
            const float lam = u / ((d == 0.f) ? 1.f : d);
            val = unstable ? (-lam * l) : 0.f;
        }
        out[LR0 + (size_t)col] = val;
        return;
    }

    // Scattered diagonal segments. Branch-minimal: both diagonals share the
    // active/unstable classification; they differ only in the unstable value
    // (alpha vs lambda) and the corner handling.
    size_t pos;
    float  val;
    if (w < W_DLOW) {
        const int k = w - W_LROW;                     // A_low diag, k = 0..8192
        if (k == NN) {
            val = 1.f;
        } else {
            const float l = lower[k];
            const float u = upper[k];
            const float a = fminf(fmaxf(alphas[k], 0.f), 1.f);
            // active -> 1 ; unstable -> a ; else 0
            val = (u > 0.f) ? ((l >= 0.f) ? 1.f : a) : 0.f;
        }
        pos = AB + (size_t)k * (size_t)(NP1 + 1);
    } else {
        const int k = w - W_DLOW;                     // A_up diag, k = 0..8191
        const float l = lower[k];
        const float u = upper[k];
        const float d = u - l;
        const float lam = u / ((d == 0.f) ? 1.f : d);
        // active -> 1 ; unstable -> lam ; else 0
        val = (u > 0.f) ? ((l >= 0.f) ? 1.f : lam) : 0.f;
        pos = AUB + (size_t)k * (size_t)(NP1 + 1);
    }
    __stcs(out + pos, val);   // streaming store: best measured for the scatter
}

extern "C" void kernel_launch(void* const* d_in, const int* in_sizes, int n_in,
                              void* d_out, int out_size) {
    const float* lower  = (const float*)d_in[0];
    const float* upper  = (const float*)d_in[1];
    const float* alphas = (const float*)d_in[2];
    float* out = (float*)d_out;

    // Full-buffer memset from the allocation base. Measured bimodal across
    // runs (~7.4 TB/s fast mode vs ~4.9 TB/s slow mode) independent of call
    // shape; fast mode is the only configuration that beats every SM-side
    // fill (those cap at ~5.6 TB/s consistently: R2/R3/R9).
    cudaMemsetAsync(d_out, 0, (size_t)out_size * sizeof(float), 0);

    const int blocks = (W_TOT + THREADS - 1) / THREADS;   // 81
    relu_relax_patch<<<blocks, THREADS>>>(lower, upper, alphas, out);
}